// round 5
// baseline (speedup 1.0000x reference)
#include <cuda_runtime.h>

// B=2, C=4, D=64, H=256, W=256; channels 1..3 of pred/trgt.
// scale(10)/(2*DELTA=10) cancels; vorticity is linear -> stencil on (pred-trgt).
// Keep voxel iff mask==1 and min over 3^3 mask neighborhood == 1.

constexpr int DN = 64, HN = 256, WN = 256;
constexpr long sD = (long)HN * WN;          // 65536
constexpr long sH = WN;                     // 256
constexpr long CS = (long)DN * HN * WN;     // 4194304
constexpr int HT = 4;                       // h rows per block
constexpr int NHT = 64;                     // ceil(254/4)
constexpr int NPART = NHT * 62 * 2;         // 7936 blocks

__device__ float2 g_part[NPART];
__device__ int g_counter;                   // zero-init; self-resets each launch

// Grid: (NHT, 62, 2)  block: 1024.  One d-plane, 4x256 output tile per block.
__global__ __launch_bounds__(1024) void vort_kernel(
    const float* __restrict__ pred,
    const float* __restrict__ trgt,
    const float* __restrict__ mask,
    float* __restrict__ out)
{
    const int tid = threadIdx.x;
    const int h0  = 1 + blockIdx.x * HT;     // first output h row
    const int d   = 1 + blockIdx.y;          // 1..62
    const int b   = blockIdx.z;

    __shared__ float zmin[HT + 2][WN];       // min over dz of mask
    __shared__ float craw[HT + 2][WN];       // mask at dz=0

    // cooperative fill: (HT+2) mask rows x 256 w, 3 dz-planes each
    {
        const float* mpl = mask + (long)b * DN * sD + (long)d * sD;
        #pragma unroll
        for (int i = tid; i < (HT + 2) * WN; i += 1024) {
            int row = i >> 8;                 // 0..5
            int w   = i & 255;
            int hm  = min(h0 - 1 + row, HN - 1);
            const float* p = mpl + (long)hm * sH + w;
            float m0 = __ldg(p - sD);
            float m1 = __ldg(p);
            float m2 = __ldg(p + sD);
            zmin[row][w] = fminf(m0, fminf(m1, m2));
            craw[row][w] = m1;
        }
    }
    __syncthreads();

    const int hh = tid >> 8;                 // 0..3
    const int w  = tid & 255;
    const int h  = h0 + hh;

    float numer = 0.0f;
    float den   = 0.0f;

    if (h <= HN - 2 && w >= 1 && w <= WN - 2) {
        float mc = craw[hh + 1][w];
        if (mc > 0.5f) {
            float c0 = fminf(zmin[hh    ][w - 1], fminf(zmin[hh    ][w], zmin[hh    ][w + 1]));
            float c1 = fminf(zmin[hh + 1][w - 1], fminf(zmin[hh + 1][w], zmin[hh + 1][w + 1]));
            float c2 = fminf(zmin[hh + 2][w - 1], fminf(zmin[hh + 2][w], zmin[hh + 2][w + 1]));
            if (fminf(c0, fminf(c1, c2)) > 0.5f) {
                den = 1.0f;
                const long pb = (long)b * 4 * CS + (long)d * sD + (long)h * sH + w;
                const float* pu = pred + pb + 1 * CS;
                const float* pv = pred + pb + 2 * CS;
                const float* pw = pred + pb + 3 * CS;
                const float* tu = trgt + pb + 1 * CS;
                const float* tv = trgt + pb + 2 * CS;
                const float* tw = trgt + pb + 3 * CS;

                float Du_D = (__ldg(pu + sD) - __ldg(tu + sD)) - (__ldg(pu - sD) - __ldg(tu - sD));
                float Du_H = (__ldg(pu + sH) - __ldg(tu + sH)) - (__ldg(pu - sH) - __ldg(tu - sH));
                float Dv_D = (__ldg(pv + sD) - __ldg(tv + sD)) - (__ldg(pv - sD) - __ldg(tv - sD));
                float Dv_W = (__ldg(pv + 1 ) - __ldg(tv + 1 )) - (__ldg(pv - 1 ) - __ldg(tv - 1 ));
                float Dw_H = (__ldg(pw + sH) - __ldg(tw + sH)) - (__ldg(pw - sH) - __ldg(tw - sH));
                float Dw_W = (__ldg(pw + 1 ) - __ldg(tw + 1 )) - (__ldg(pw - 1 ) - __ldg(tw - 1 ));

                float vx = Dw_H - Dv_D;
                float vy = Du_D - Dw_W;
                float vz = Dv_W - Du_H;
                numer = sqrtf(vx * vx + vy * vy + vz * vz);
            }
        }
    }

    // ---- block reduction ----
    #pragma unroll
    for (int s = 16; s; s >>= 1) {
        numer += __shfl_down_sync(0xffffffffu, numer, s);
        den   += __shfl_down_sync(0xffffffffu, den,   s);
    }
    __shared__ float wn[32], wd[32];
    const int wid  = tid >> 5;
    const int lane = tid & 31;
    if (lane == 0) { wn[wid] = numer; wd[wid] = den; }
    __syncthreads();

    __shared__ bool isLast;
    if (wid == 0) {
        float n2 = wn[lane];
        float d2 = wd[lane];
        #pragma unroll
        for (int s = 16; s; s >>= 1) {
            n2 += __shfl_down_sync(0xffffffffu, n2, s);
            d2 += __shfl_down_sync(0xffffffffu, d2, s);
        }
        if (lane == 0) {
            const int bid = blockIdx.x + NHT * (blockIdx.y + 62 * blockIdx.z);
            g_part[bid] = make_float2(n2, d2);
            __threadfence();
            int prev = atomicAdd(&g_counter, 1);
            isLast = (prev == NPART - 1);
        }
    }
    __syncthreads();

    // ---- last block finalizes (fused; no tail kernel) ----
    if (isLast) {
        __threadfence();
        double n = 0.0, dd = 0.0;
        for (int i = tid; i < NPART; i += 1024) {
            float2 p = g_part[i];
            n  += (double)p.x;
            dd += (double)p.y;
        }
        #pragma unroll
        for (int s = 16; s; s >>= 1) {
            n  += __shfl_down_sync(0xffffffffu, n,  s);
            dd += __shfl_down_sync(0xffffffffu, dd, s);
        }
        __shared__ double sn[32], sd[32];
        if (lane == 0) { sn[wid] = n; sd[wid] = dd; }
        __syncthreads();
        if (wid == 0) {
            n  = sn[lane];
            dd = sd[lane];
            #pragma unroll
            for (int s = 16; s; s >>= 1) {
                n  += __shfl_down_sync(0xffffffffu, n,  s);
                dd += __shfl_down_sync(0xffffffffu, dd, s);
            }
            if (lane == 0) {
                out[0] = (float)(n / dd);
                g_counter = 0;             // reset for next graph replay
            }
        }
    }
}

extern "C" void kernel_launch(void* const* d_in, const int* in_sizes, int n_in,
                              void* d_out, int out_size) {
    const float* pred = (const float*)d_in[0];   // predicts (2,4,64,256,256)
    const float* trgt = (const float*)d_in[1];   // targets  (2,4,64,256,256)
    const float* mask = (const float*)d_in[2];   // masks    (2,1,64,256,256)
    float* out = (float*)d_out;

    dim3 grid(NHT, 62, 2);
    vort_kernel<<<grid, 1024>>>(pred, trgt, mask, out);
}

// round 6
// speedup vs baseline: 1.6075x; 1.6075x over previous
#include <cuda_runtime.h>

// B=2, C=4, D=64, H=256, W=256; channels 1..3 of pred/trgt.
// scale(10)/(2*DELTA=10) cancels; vorticity linear -> stencil on (pred-trgt).
// keep voxel  <=>  min over 3^3 mask neighborhood == 1 (center included).

constexpr int DN = 64, HN = 256, WN = 256;
constexpr long sD = (long)HN * WN;          // 65536
constexpr long sH = WN;                     // 256
constexpr long CS = (long)DN * HN * WN;     // 4194304
constexpr int HT = 4;                       // h rows per block
constexpr int NHX = 64;                     // ceil(254/4)
constexpr int NPART = NHX * 62 * 2;         // 7936 blocks

__device__ float2 g_part[NPART];
__device__ int g_counter;                   // zero-init; self-resets each launch

__device__ __forceinline__ float4 ld4(const float* p) {
    return __ldg(reinterpret_cast<const float4*>(p));
}
__device__ __forceinline__ float4 min4(float4 a, float4 b) {
    return make_float4(fminf(a.x,b.x), fminf(a.y,b.y), fminf(a.z,b.z), fminf(a.w,b.w));
}
__device__ __forceinline__ float4 sub4(float4 a, float4 b) {
    return make_float4(a.x-b.x, a.y-b.y, a.z-b.z, a.w-b.w);
}
// (p1 - t1) - (p0 - t0), all float4
__device__ __forceinline__ float4 dd4(const float* p, const float* t, long off) {
    return sub4(sub4(ld4(p + off), ld4(t + off)), sub4(ld4(p - off), ld4(t - off)));
}

// Grid: (NHX, 62, 2)  block: 256 = 4 h-rows x 64 w-threads (float4 each).
__global__ __launch_bounds__(256) void vort_kernel(
    const float* __restrict__ pred,
    const float* __restrict__ trgt,
    const float* __restrict__ mask,
    float* __restrict__ out)
{
    const int tid = threadIdx.x;
    const int row = tid >> 6;                // 0..3
    const int t   = tid & 63;                // w-group
    const int w4  = t << 2;                  // first w of this thread
    const int h   = 1 + blockIdx.x * HT + row;
    const int hc  = min(h, HN - 2);          // clamp for loads; h>254 discarded
    const int d   = 1 + blockIdx.y;          // 1..62
    const int b   = blockIdx.z;

    // ---- mask: per-w column min over 3x3 (dz,dy) ----
    const float* mb = mask + (long)b * DN * sD + (long)d * sD + (long)hc * sH + w4;
    float4 cm = make_float4(1e9f, 1e9f, 1e9f, 1e9f);
    #pragma unroll
    for (int dz = -1; dz <= 1; dz++)
        #pragma unroll
        for (int dy = -1; dy <= 1; dy++)
            cm = min4(cm, ld4(mb + (long)dz * sD + (long)dy * sH));

    __shared__ float cs[HT][WN];
    *reinterpret_cast<float4*>(&cs[row][w4]) = cm;

    // ---- stencil on (pred - trgt), unconditional (bytes are free: every
    // cache line is touched anyway; this removes the mask->load dependency) ----
    const long pb = (long)b * 4 * CS + (long)d * sD + (long)hc * sH + w4;
    const float* pu = pred + pb + 1 * CS;
    const float* pv = pred + pb + 2 * CS;
    const float* pw = pred + pb + 3 * CS;
    const float* tu = trgt + pb + 1 * CS;
    const float* tv = trgt + pb + 2 * CS;
    const float* tw = trgt + pb + 3 * CS;

    float4 du_d = dd4(pu, tu, sD);           // du/dD
    float4 du_h = dd4(pu, tu, sH);           // du/dH
    float4 dv_d = dd4(pv, tv, sD);           // dv/dD
    float4 dw_h = dd4(pw, tw, sH);           // dw/dH

    float4 vc = sub4(ld4(pv), ld4(tv));      // center (v_p - v_t)
    float4 wc = sub4(ld4(pw), ld4(tw));      // center (w_p - w_t)
    const long eL = (t > 0)  ? -1 : 0;       // clamped edge offsets (unused comps discarded)
    const long eR = (t < 63) ?  4 : 3;
    float vL = __ldg(pv + eL) - __ldg(tv + eL);
    float vR = __ldg(pv + eR) - __ldg(tv + eR);
    float wL = __ldg(pw + eL) - __ldg(tw + eL);
    float wR = __ldg(pw + eR) - __ldg(tw + eR);

    float4 dv_w = make_float4(vc.y - vL, vc.z - vc.x, vc.w - vc.y, vR - vc.z);
    float4 dw_w = make_float4(wc.y - wL, wc.z - wc.x, wc.w - wc.y, wR - wc.z);

    // vor_x = dw/dH - dv/dD ; vor_y = du/dD - dw/dW ; vor_z = dv/dW - du/dH
    float4 vx = sub4(dw_h, dv_d);
    float4 vy = sub4(du_d, dw_w);
    float4 vz = sub4(dv_w, du_h);

    __syncthreads();

    float numer = 0.0f;
    float den   = 0.0f;
    const bool hvalid = (h <= HN - 2);
    #pragma unroll
    for (int i = 0; i < 4; i++) {
        const int w = w4 + i;
        bool valid = hvalid && (w >= 1) && (w <= WN - 2);
        float a = cs[row][max(w - 1, 0)];
        float c = cs[row][w];
        float e = cs[row][min(w + 1, WN - 1)];
        if (valid && fminf(a, fminf(c, e)) > 0.5f) {
            float x = (i==0)?vx.x:(i==1)?vx.y:(i==2)?vx.z:vx.w;
            float y = (i==0)?vy.x:(i==1)?vy.y:(i==2)?vy.z:vy.w;
            float z = (i==0)?vz.x:(i==1)?vz.y:(i==2)?vz.z:vz.w;
            numer += sqrtf(x * x + y * y + z * z);
            den   += 1.0f;
        }
    }

    // ---- block reduction (8 warps) ----
    #pragma unroll
    for (int s = 16; s; s >>= 1) {
        numer += __shfl_down_sync(0xffffffffu, numer, s);
        den   += __shfl_down_sync(0xffffffffu, den,   s);
    }
    __shared__ float wn[8], wd[8];
    const int wid  = tid >> 5;
    const int lane = tid & 31;
    if (lane == 0) { wn[wid] = numer; wd[wid] = den; }
    __syncthreads();

    __shared__ bool isLast;
    if (wid == 0) {
        float n2 = (lane < 8) ? wn[lane] : 0.0f;
        float d2 = (lane < 8) ? wd[lane] : 0.0f;
        #pragma unroll
        for (int s = 4; s; s >>= 1) {
            n2 += __shfl_down_sync(0xffffffffu, n2, s);
            d2 += __shfl_down_sync(0xffffffffu, d2, s);
        }
        if (lane == 0) {
            const int bid = blockIdx.x + NHX * (blockIdx.y + 62 * blockIdx.z);
            g_part[bid] = make_float2(n2, d2);
            __threadfence();
            int prev = atomicAdd(&g_counter, 1);
            isLast = (prev == NPART - 1);
        }
    }
    __syncthreads();

    // ---- last block finalizes (no tail kernel) ----
    if (isLast) {
        __threadfence();
        double n = 0.0, dd = 0.0;
        for (int i = tid; i < NPART; i += 256) {
            float2 p = g_part[i];
            n  += (double)p.x;
            dd += (double)p.y;
        }
        #pragma unroll
        for (int s = 16; s; s >>= 1) {
            n  += __shfl_down_sync(0xffffffffu, n,  s);
            dd += __shfl_down_sync(0xffffffffu, dd, s);
        }
        __shared__ double sn[8], sd[8];
        if (lane == 0) { sn[wid] = n; sd[wid] = dd; }
        __syncthreads();
        if (wid == 0) {
            n  = (lane < 8) ? sn[lane] : 0.0;
            dd = (lane < 8) ? sd[lane] : 0.0;
            #pragma unroll
            for (int s = 4; s; s >>= 1) {
                n  += __shfl_down_sync(0xffffffffu, n,  s);
                dd += __shfl_down_sync(0xffffffffu, dd, s);
            }
            if (lane == 0) {
                out[0] = (float)(n / dd);
                g_counter = 0;              // reset for next graph replay
            }
        }
    }
}

extern "C" void kernel_launch(void* const* d_in, const int* in_sizes, int n_in,
                              void* d_out, int out_size) {
    const float* pred = (const float*)d_in[0];   // predicts (2,4,64,256,256)
    const float* trgt = (const float*)d_in[1];   // targets  (2,4,64,256,256)
    const float* mask = (const float*)d_in[2];   // masks    (2,1,64,256,256)
    float* out = (float*)d_out;

    dim3 grid(NHX, 62, 2);
    vort_kernel<<<grid, 256>>>(pred, trgt, mask, out);
}